// round 15
// baseline (speedup 1.0000x reference)
#include <cuda_runtime.h>
#include <math.h>
#include <cstdint>

#define BB 16
#define TT 4096
#define CC 8
#define FF 64
#define KW 11
#define LL 4096
#define NTT 32            // t-tiles of 128 per batch

// Scratch (device globals; no runtime allocation)
__device__ __align__(16) float g_P[BB * FF * TT];        // 16 MB softmax, [B][F][T]
__device__ __align__(16) float g_U[TT * LL];             // 64 MB: posenc@W + bias, [T][L]
__device__ __align__(16) float g_Wt[LL * FF];            // 1 MB: W transposed [l][k], tf32-rounded
__device__ __align__(16) float g_part4[4 * NTT * BB * LL]; // 32 MB per-(wt,ttile) partial T-sums

// ---------------- helpers ----------------
__device__ __forceinline__ unsigned long long packff(float lo, float hi) {
    unsigned long long r;
    asm("mov.b64 %0, {%1, %2};" : "=l"(r) : "f"(lo), "f"(hi));
    return r;
}
__device__ __forceinline__ void unpackff(unsigned long long v, float& lo, float& hi) {
    asm("mov.b64 {%0, %1}, %2;" : "=f"(lo), "=f"(hi) : "l"(v));
}
__device__ __forceinline__ void ffma2(unsigned long long& d, unsigned long long a, unsigned long long b) {
    asm("fma.rn.f32x2 %0, %1, %2, %0;" : "+l"(d) : "l"(a), "l"(b));
}
__device__ __forceinline__ float tf32r(float v) {
    uint32_t r;
    asm("cvt.rn.tf32.f32 %0, %1;" : "=r"(r) : "f"(v));
    return __uint_as_float(r);
}
__device__ __forceinline__ uint32_t smem_u32(const void* p) {
    uint32_t a;
    asm("{ .reg .u64 t; cvta.to.shared.u64 t, %1; cvt.u32.u64 %0, t; }" : "=r"(a) : "l"(p));
    return a;
}
__device__ __forceinline__ void cp_async16(uint32_t dst, const void* src) {
    asm volatile("cp.async.cg.shared.global [%0], [%1], 16;" :: "r"(dst), "l"(src) : "memory");
}
__device__ __forceinline__ void ldsm_x4(uint32_t r[4], uint32_t addr) {
    asm volatile("ldmatrix.sync.aligned.m8n8.x4.shared.b16 {%0,%1,%2,%3}, [%4];"
        : "=r"(r[0]), "=r"(r[1]), "=r"(r[2]), "=r"(r[3]) : "r"(addr));
}
__device__ __forceinline__ void mma_tf32(float c[4], const uint32_t a[4], const uint32_t b[2]) {
    asm volatile("mma.sync.aligned.m16n8k8.row.col.f32.tf32.tf32.f32 "
        "{%0,%1,%2,%3}, {%4,%5,%6,%7}, {%8,%9}, {%0,%1,%2,%3};"
        : "+f"(c[0]), "+f"(c[1]), "+f"(c[2]), "+f"(c[3])
        : "r"(a[0]), "r"(a[1]), "r"(a[2]), "r"(a[3]), "r"(b[0]), "r"(b[1]));
}

// ---------------- Kernel 0: W transpose + tf32 round -> g_Wt[l][k] ----------------
__global__ __launch_bounds__(256) void prep_wt_kernel(const float* __restrict__ W) // [F,L]
{
    int idx = blockIdx.x * 256 + threadIdx.x;
    int k = idx >> 12;
    int l = idx & (LL - 1);
    g_Wt[(size_t)l * FF + k] = tf32r(W[idx]);
}

// ---------------- Kernel 1: Conv1D (SAME) + BatchNorm -> g_P[b][f][t] (pre-softmax) ----------------
__global__ __launch_bounds__(256) void conv_bn_kernel(
    const float* __restrict__ x, const float* __restrict__ conv_w,
    const float* __restrict__ conv_b, const float* __restrict__ gamma,
    const float* __restrict__ beta, const float* __restrict__ mean,
    const float* __restrict__ var)
{
    __shared__ __align__(16) float ws[KW * CC * FF];
    __shared__ __align__(16) float xs[266][9];

    const int tid = threadIdx.x;
    const int b  = blockIdx.y;
    const int t0 = blockIdx.x * 256;

    for (int i = tid; i < (KW * CC * FF) / 4; i += 256)
        ((float4*)ws)[i] = ((const float4*)conv_w)[i];

    for (int i = tid; i < 266; i += 256) {
        int t = t0 + i - 5;
        if (t >= 0 && t < TT) {
            const float* xp = x + ((size_t)b * TT + t) * CC;
            #pragma unroll
            for (int c = 0; c < CC; c++) xs[i][c] = xp[c];
        } else {
            #pragma unroll
            for (int c = 0; c < CC; c++) xs[i][c] = 0.f;
        }
    }
    __syncthreads();

    const int t = t0 + tid;
    for (int fo = 0; fo < FF; fo += 8) {
        float acc[8];
        #pragma unroll
        for (int j = 0; j < 8; j++) acc[j] = conv_b[fo + j];
        #pragma unroll
        for (int k = 0; k < KW; k++) {
            #pragma unroll
            for (int c = 0; c < CC; c++) {
                float xv = xs[tid + k][c];
                const float* wp = &ws[(k * CC + c) * FF + fo];
                #pragma unroll
                for (int j = 0; j < 8; j++) acc[j] = fmaf(xv, wp[j], acc[j]);
            }
        }
        #pragma unroll
        for (int j = 0; j < 8; j++) {
            int f = fo + j;
            float inv = rsqrtf(var[f] + 1e-3f);
            g_P[((size_t)b * FF + f) * TT + t] = (acc[j] - mean[f]) * inv * gamma[f] + beta[f];
        }
    }
}

// ---------------- Kernel 2: softmax over T ----------------
__global__ __launch_bounds__(256) void softmax_kernel()
{
    const int bf = blockIdx.x;
    float* row = g_P + (size_t)bf * TT;
    const int tid = threadIdx.x;

    float v[16];
    #pragma unroll
    for (int i = 0; i < 16; i++) v[i] = row[tid + i * 256];

    float m = v[0];
    #pragma unroll
    for (int i = 1; i < 16; i++) m = fmaxf(m, v[i]);

    __shared__ float sred[8];
    #pragma unroll
    for (int o = 16; o > 0; o >>= 1) m = fmaxf(m, __shfl_xor_sync(0xffffffffu, m, o));
    if ((tid & 31) == 0) sred[tid >> 5] = m;
    __syncthreads();
    m = sred[0];
    #pragma unroll
    for (int w = 1; w < 8; w++) m = fmaxf(m, sred[w]);

    float s = 0.f;
    #pragma unroll
    for (int i = 0; i < 16; i++) { v[i] = __expf(v[i] - m); s += v[i]; }
    #pragma unroll
    for (int o = 16; o > 0; o >>= 1) s += __shfl_xor_sync(0xffffffffu, s, o);
    __syncthreads();
    if ((tid & 31) == 0) sred[tid >> 5] = s;
    __syncthreads();
    s = 0.f;
    #pragma unroll
    for (int w = 0; w < 8; w++) s += sred[w];

    float inv = __fdividef(1.f, s);
    #pragma unroll
    for (int i = 0; i < 16; i++) row[tid + i * 256] = v[i] * inv;
}

// ---------------- Kernel 3: U = posenc @ W + bias (fp32 FFMA2; analytic posenc) ----------------
__global__ __launch_bounds__(256, 2) void u_gemm_kernel(
    const float* __restrict__ W,     // [F, L]
    const float* __restrict__ bias)  // [L]
{
    extern __shared__ __align__(16) float smem[];
    float (*Asm)[128] = (float(*)[128])smem;               // 64 k x 128 t
    float (*Wsm)[128] = (float(*)[128])(smem + 64 * 128);  // 64 k x 128 l
    __shared__ float ts[FF];

    const int tid  = threadIdx.x;
    const int tgrp = tid & 15;
    const int lgrp = tid >> 4;
    const int l0   = blockIdx.x * 128;
    const int tseg = blockIdx.y;

    if (tid < FF)
        ts[tid] = (float)pow(1.0e-4, (double)(tid & ~1) / 64.0);

    for (int i = tid; i < (64 * 128) / 4; i += 256) {
        int fr = i >> 5;
        int c4 = i & 31;
        *(float4*)&Wsm[fr][c4 * 4] = *(const float4*)&W[(size_t)fr * LL + l0 + c4 * 4];
    }

    ulonglong2 bq0 = *(const ulonglong2*)&bias[l0 + lgrp * 8];
    ulonglong2 bq1 = *(const ulonglong2*)&bias[l0 + lgrp * 8 + 4];
    unsigned long long bp[4] = {bq0.x, bq0.y, bq1.x, bq1.y};

    for (int ch = 0; ch < 4; ch++) {
        const int t0 = tseg * 512 + ch * 128;
        __syncthreads();
        for (int i = tid; i < 64 * 128; i += 256) {
            int k = i >> 7, t = i & 127;
            float ang = (float)(t0 + t) * ts[k];
            Asm[k][t] = (k & 1) ? cosf(ang) : sinf(ang);
        }
        __syncthreads();

        unsigned long long acc[8][4];
        #pragma unroll
        for (int i = 0; i < 8; i++)
            #pragma unroll
            for (int j = 0; j < 4; j++) acc[i][j] = bp[j];

        #pragma unroll 8
        for (int k = 0; k < 64; k++) {
            const ulonglong2* wq = (const ulonglong2*)&Wsm[k][lgrp * 8];
            ulonglong2 w01 = wq[0];
            ulonglong2 w23 = wq[1];
            float4 a0 = *(const float4*)&Asm[k][tgrp * 8];
            float4 a1 = *(const float4*)&Asm[k][tgrp * 8 + 4];
            float af[8] = {a0.x, a0.y, a0.z, a0.w, a1.x, a1.y, a1.z, a1.w};
            #pragma unroll
            for (int i = 0; i < 8; i++) {
                unsigned long long ap = packff(af[i], af[i]);
                ffma2(acc[i][0], ap, w01.x);
                ffma2(acc[i][1], ap, w01.y);
                ffma2(acc[i][2], ap, w23.x);
                ffma2(acc[i][3], ap, w23.y);
            }
        }

        #pragma unroll
        for (int i = 0; i < 8; i++) {
            float v0, v1, v2, v3, v4, v5, v6, v7;
            unpackff(acc[i][0], v0, v1);
            unpackff(acc[i][1], v2, v3);
            unpackff(acc[i][2], v4, v5);
            unpackff(acc[i][3], v6, v7);
            float* up = &g_U[(size_t)(t0 + tgrp * 8 + i) * LL + l0 + lgrp * 8];
            *(float4*)up       = make_float4(v0, v1, v2, v3);
            *(float4*)(up + 4) = make_float4(v4, v5, v6, v7);
        }
    }
}

// ---------------- Kernel 4: S = P @ W (tf32 mma, 3-stage pipelined l-chunks) ----------------
// grid (b=16, ttile=32, lq=4); block 256 = 8 warps (4 t x 2 l). P tile resident;
// 16 l-chunks of 64 l, W TRIPLE-buffered via cp.async (wait_group 1 => wait is ~free);
// U prefetched to regs; per-chunk tail: shfl reduce + direct g_part4 store (NO 2nd barrier).
#define PS 68
#define SG_SMEM ((128 * PS + 3 * 64 * PS) * 4)   // 87040 B

__global__ __launch_bounds__(256, 2) void sgemm_tc_kernel()
{
    extern __shared__ __align__(16) float sm[];
    float* Psm = sm;                          // [128 t][PS]

    const int tid = threadIdx.x;
    const int b     = blockIdx.x;
    const int ttile = blockIdx.y;
    const int lq    = blockIdx.z;
    const int t0    = ttile * 128;
    const int lbase = lq * 1024;

    // fill Psm once: read coalesced along t, store [t][f] tf32
    for (int i = tid; i < 128 * 64; i += 256) {
        int f = i >> 7, t = i & 127;
        Psm[t * PS + f] = tf32r(g_P[((size_t)b * FF + f) * TT + t0 + t]);
    }

    const int lane = tid & 31;
    const int w    = tid >> 5;
    const int wt   = w & 3;           // t-warp (32 t)
    const int wl   = w >> 2;          // l-warp (32 l)
    const int g    = lane >> 2;
    const int tq   = lane & 3;

    const int rA = lane & 15;
    const int cA = (lane >> 4) * 16;
    const int rB = (lane & 7) + ((lane >> 4) & 1) * 8;
    const int cB = ((lane >> 3) & 1) * 16;

    const uint32_t sbP = smem_u32(Psm);
    const uint32_t sbW = sbP + 128 * PS * 4;
    uint32_t addrA0 = sbP + (uint32_t)((wt * 32 + rA) * PS) * 4 + cA;
    uint32_t addrA1 = addrA0 + 16 * PS * 4;

    // prologue: cp.async W chunks 0 and 1 into buffers 0,1
    #pragma unroll
    for (int pc = 0; pc < 2; pc++) {
        const float* src = g_Wt + (size_t)(lbase + pc * 64) * FF;
        uint32_t dst = sbW + (uint32_t)pc * (64 * PS * 4);
        #pragma unroll
        for (int j = 0; j < 4; j++) {
            int i = tid + j * 256;
            int row = i >> 4, seg = i & 15;
            cp_async16(dst + row * (PS * 4) + seg * 16, src + row * FF + seg * 4);
        }
        asm volatile("cp.async.commit_group;" ::: "memory");
    }

    const int tbase = t0 + wt * 32 + g;

    for (int c = 0; c < 16; c++) {
        if (c < 14)
            asm volatile("cp.async.wait_group 1;" ::: "memory");   // chunk c committed 2 ago
        else
            asm volatile("cp.async.wait_group 0;" ::: "memory");   // drain tail
        __syncthreads();              // buf[c%3] ready; prior readers of buf[(c+2)%3]=buf[(c-1)%3] done

        const uint32_t wbuf = sbW + (uint32_t)(c % 3) * (64 * PS * 4);

        if (c + 2 < 16) {             // prefetch chunk c+2 into buffer (c+2)%3
            const float* src = g_Wt + (size_t)(lbase + (c + 2) * 64) * FF;
            uint32_t dst = sbW + (uint32_t)((c + 2) % 3) * (64 * PS * 4);
            #pragma unroll
            for (int j = 0; j < 4; j++) {
                int i = tid + j * 256;
                int row = i >> 4, seg = i & 15;
                cp_async16(dst + row * (PS * 4) + seg * 16, src + row * FF + seg * 4);
            }
            asm volatile("cp.async.commit_group;" ::: "memory");
        }

        const int l0    = lbase + c * 64;
        const int cbase = l0 + wl * 32 + 2 * tq;

        // U prefetch (latency hides under the mainloop)
        float2 ur[2][4][2];
        #pragma unroll
        for (int m = 0; m < 2; m++)
            #pragma unroll
            for (int n = 0; n < 4; n++) {
                int col = cbase + n * 8;
                ur[m][n][0] = *(const float2*)&g_U[(size_t)(tbase + m * 16) * LL + col];
                ur[m][n][1] = *(const float2*)&g_U[(size_t)(tbase + m * 16 + 8) * LL + col];
            }

        uint32_t addrB0 = wbuf + (uint32_t)((wl * 32 + rB) * PS) * 4 + cB;
        uint32_t addrB1 = addrB0 + 16 * PS * 4;

        float acc[2][4][4];
        #pragma unroll
        for (int m = 0; m < 2; m++)
            #pragma unroll
            for (int n = 0; n < 4; n++)
                #pragma unroll
                for (int j = 0; j < 4; j++) acc[m][n][j] = 0.f;

        #pragma unroll
        for (int ks = 0; ks < 8; ks++) {
            uint32_t fa0[4], fa1[4], fb0[4], fb1[4];
            ldsm_x4(fa0, addrA0 + ks * 32);
            ldsm_x4(fa1, addrA1 + ks * 32);
            ldsm_x4(fb0, addrB0 + ks * 32);
            ldsm_x4(fb1, addrB1 + ks * 32);
            mma_tf32(acc[0][0], fa0, &fb0[0]);
            mma_tf32(acc[0][1], fa0, &fb0[2]);
            mma_tf32(acc[0][2], fa0, &fb1[0]);
            mma_tf32(acc[0][3], fa0, &fb1[2]);
            mma_tf32(acc[1][0], fa1, &fb0[0]);
            mma_tf32(acc[1][1], fa1, &fb0[2]);
            mma_tf32(acc[1][2], fa1, &fb1[0]);
            mma_tf32(acc[1][3], fa1, &fb1[2]);
        }

        // epilogue: y = acc + U; d = (1-e^-y)/(1+e^-y); accumulate over t
        float colsum[8];
        #pragma unroll
        for (int i = 0; i < 8; i++) colsum[i] = 0.f;

        #pragma unroll
        for (int m = 0; m < 2; m++) {
            #pragma unroll
            for (int n = 0; n < 4; n++) {
                float y00 = acc[m][n][0] + ur[m][n][0].x;
                float y01 = acc[m][n][1] + ur[m][n][0].y;
                float y10 = acc[m][n][2] + ur[m][n][1].x;
                float y11 = acc[m][n][3] + ur[m][n][1].y;
                float e;
                e = __expf(-y00); colsum[2 * n]     += __fdividef(1.f - e, 1.f + e);
                e = __expf(-y10); colsum[2 * n]     += __fdividef(1.f - e, 1.f + e);
                e = __expf(-y01); colsum[2 * n + 1] += __fdividef(1.f - e, 1.f + e);
                e = __expf(-y11); colsum[2 * n + 1] += __fdividef(1.f - e, 1.f + e);
            }
        }

        #pragma unroll
        for (int off = 4; off <= 16; off <<= 1)
            #pragma unroll
            for (int i = 0; i < 8; i++)
                colsum[i] += __shfl_xor_sync(0xffffffffu, colsum[i], off);

        // direct per-wt partial store (no second barrier, no smem reduce)
        if (g == 0) {
            float* gp = &g_part4[(((size_t)wt * NTT + ttile) * BB + b) * LL + cbase];
            #pragma unroll
            for (int n = 0; n < 4; n++) {
                gp[n * 8]     = colsum[2 * n];
                gp[n * 8 + 1] = colsum[2 * n + 1];
            }
        }
    }
}

// ---------------- Kernel 5: Gaussian shifting layer (banded) ----------------
__global__ __launch_bounds__(256) void warp_out_kernel(
    const float* __restrict__ x, float* __restrict__ out)
{
    const int idx = blockIdx.x * 256 + threadIdx.x;   // b*L + l
    const int b = idx >> 12;
    const int l = idx & (LL - 1);

    float sh = 0.f;
    #pragma unroll 8
    for (int s = 0; s < 4 * NTT; s++) sh += g_part4[(size_t)s * BB * LL + idx];

    const float center = ((float)(l + 1) + sh) * ((float)TT / (float)LL);

    int tlo = (int)ceilf(center - 7.f);
    int thi = (int)floorf(center + 7.f);
    if (tlo < 1)  tlo = 1;
    if (thi > TT) thi = TT;

    float acc[8] = {0.f, 0.f, 0.f, 0.f, 0.f, 0.f, 0.f, 0.f};
    const float* xb = x + (size_t)b * TT * CC;
    for (int t = tlo; t <= thi; t++) {
        float d = (float)t - center;
        float wgt = __expf(-d * d);
        const float4* xp = (const float4*)(xb + (size_t)(t - 1) * CC);
        float4 x0 = xp[0];
        float4 x1 = xp[1];
        acc[0] = fmaf(wgt, x0.x, acc[0]);
        acc[1] = fmaf(wgt, x0.y, acc[1]);
        acc[2] = fmaf(wgt, x0.z, acc[2]);
        acc[3] = fmaf(wgt, x0.w, acc[3]);
        acc[4] = fmaf(wgt, x1.x, acc[4]);
        acc[5] = fmaf(wgt, x1.y, acc[5]);
        acc[6] = fmaf(wgt, x1.z, acc[6]);
        acc[7] = fmaf(wgt, x1.w, acc[7]);
    }

    const float inv = (float)(1.0 / 1.772637204826652);
    float4* op = (float4*)(out + (size_t)idx * CC);
    op[0] = make_float4(acc[0] * inv, acc[1] * inv, acc[2] * inv, acc[3] * inv);
    op[1] = make_float4(acc[4] * inv, acc[5] * inv, acc[6] * inv, acc[7] * inv);
}

// ---------------- launch ----------------
extern "C" void kernel_launch(void* const* d_in, const int* in_sizes, int n_in,
                              void* d_out, int out_size)
{
    const float* x       = (const float*)d_in[0];
    const float* conv_w  = (const float*)d_in[1];
    const float* conv_b  = (const float*)d_in[2];
    const float* gamma   = (const float*)d_in[3];
    const float* beta    = (const float*)d_in[4];
    const float* mean    = (const float*)d_in[5];
    const float* var     = (const float*)d_in[6];
    const float* dense_w = (const float*)d_in[7];
    const float* dense_b = (const float*)d_in[8];
    float* out = (float*)d_out;

    const int u_smem = 64 * 128 * sizeof(float) * 2;   // 64 KB
    cudaFuncSetAttribute(u_gemm_kernel,
                         cudaFuncAttributeMaxDynamicSharedMemorySize, u_smem);
    cudaFuncSetAttribute(sgemm_tc_kernel,
                         cudaFuncAttributeMaxDynamicSharedMemorySize, SG_SMEM);

    prep_wt_kernel<<<(FF * LL) / 256, 256>>>(dense_w);
    conv_bn_kernel<<<dim3(TT / 256, BB), 256>>>(x, conv_w, conv_b, gamma, beta, mean, var);
    softmax_kernel<<<BB * FF, 256>>>();
    u_gemm_kernel<<<dim3(LL / 128, TT / 512), 256, u_smem>>>(dense_w, dense_b);
    sgemm_tc_kernel<<<dim3(BB, NTT, 4), 256, SG_SMEM>>>();
    warp_out_kernel<<<(BB * LL) / 256, 256>>>(x, out);
}

// round 16
// speedup vs baseline: 1.1578x; 1.1578x over previous
#include <cuda_runtime.h>
#include <math.h>
#include <cstdint>

#define BB 16
#define TT 4096
#define CC 8
#define FF 64
#define KW 11
#define LL 4096
#define NTT 32            // t-tiles of 128 per batch

// Scratch (device globals; no runtime allocation)
__device__ __align__(16) float g_P[BB * FF * TT];       // 16 MB softmax, [B][F][T]
__device__ __align__(16) float g_U[TT * LL];            // 64 MB: posenc@W + bias, [T][L]
__device__ __align__(16) float g_Wt[LL * FF];           // 1 MB: W transposed [l][k], tf32-rounded
__device__ __align__(16) float g_part[NTT * BB * LL];   // 8 MB partial T-sums

// ---------------- helpers ----------------
__device__ __forceinline__ unsigned long long packff(float lo, float hi) {
    unsigned long long r;
    asm("mov.b64 %0, {%1, %2};" : "=l"(r) : "f"(lo), "f"(hi));
    return r;
}
__device__ __forceinline__ void unpackff(unsigned long long v, float& lo, float& hi) {
    asm("mov.b64 {%0, %1}, %2;" : "=f"(lo), "=f"(hi) : "l"(v));
}
__device__ __forceinline__ void ffma2(unsigned long long& d, unsigned long long a, unsigned long long b) {
    asm("fma.rn.f32x2 %0, %1, %2, %0;" : "+l"(d) : "l"(a), "l"(b));
}
__device__ __forceinline__ float tf32r(float v) {
    uint32_t r;
    asm("cvt.rn.tf32.f32 %0, %1;" : "=r"(r) : "f"(v));
    return __uint_as_float(r);
}
__device__ __forceinline__ uint32_t smem_u32(const void* p) {
    uint32_t a;
    asm("{ .reg .u64 t; cvta.to.shared.u64 t, %1; cvt.u32.u64 %0, t; }" : "=r"(a) : "l"(p));
    return a;
}
__device__ __forceinline__ void cp_async16(uint32_t dst, const void* src) {
    asm volatile("cp.async.cg.shared.global [%0], [%1], 16;" :: "r"(dst), "l"(src) : "memory");
}
__device__ __forceinline__ void ldsm_x4(uint32_t r[4], uint32_t addr) {
    asm volatile("ldmatrix.sync.aligned.m8n8.x4.shared.b16 {%0,%1,%2,%3}, [%4];"
        : "=r"(r[0]), "=r"(r[1]), "=r"(r[2]), "=r"(r[3]) : "r"(addr));
}
__device__ __forceinline__ void mma_tf32(float c[4], const uint32_t a[4], const uint32_t b[2]) {
    asm volatile("mma.sync.aligned.m16n8k8.row.col.f32.tf32.tf32.f32 "
        "{%0,%1,%2,%3}, {%4,%5,%6,%7}, {%8,%9}, {%0,%1,%2,%3};"
        : "+f"(c[0]), "+f"(c[1]), "+f"(c[2]), "+f"(c[3])
        : "r"(a[0]), "r"(a[1]), "r"(a[2]), "r"(a[3]), "r"(b[0]), "r"(b[1]));
}

// ---------------- Kernel 0: W transpose + tf32 round -> g_Wt[l][k] ----------------
__global__ __launch_bounds__(256) void prep_wt_kernel(const float* __restrict__ W) // [F,L]
{
    int idx = blockIdx.x * 256 + threadIdx.x;
    int k = idx >> 12;
    int l = idx & (LL - 1);
    g_Wt[(size_t)l * FF + k] = tf32r(W[idx]);
}

// ---------------- Kernel 1: Conv1D (SAME) + BatchNorm -> g_P[b][f][t] (pre-softmax) ----------------
__global__ __launch_bounds__(256) void conv_bn_kernel(
    const float* __restrict__ x, const float* __restrict__ conv_w,
    const float* __restrict__ conv_b, const float* __restrict__ gamma,
    const float* __restrict__ beta, const float* __restrict__ mean,
    const float* __restrict__ var)
{
    __shared__ __align__(16) float ws[KW * CC * FF];
    __shared__ __align__(16) float xs[266][9];

    const int tid = threadIdx.x;
    const int b  = blockIdx.y;
    const int t0 = blockIdx.x * 256;

    for (int i = tid; i < (KW * CC * FF) / 4; i += 256)
        ((float4*)ws)[i] = ((const float4*)conv_w)[i];

    for (int i = tid; i < 266; i += 256) {
        int t = t0 + i - 5;
        if (t >= 0 && t < TT) {
            const float* xp = x + ((size_t)b * TT + t) * CC;
            #pragma unroll
            for (int c = 0; c < CC; c++) xs[i][c] = xp[c];
        } else {
            #pragma unroll
            for (int c = 0; c < CC; c++) xs[i][c] = 0.f;
        }
    }
    __syncthreads();

    const int t = t0 + tid;
    for (int fo = 0; fo < FF; fo += 8) {
        float acc[8];
        #pragma unroll
        for (int j = 0; j < 8; j++) acc[j] = conv_b[fo + j];
        #pragma unroll
        for (int k = 0; k < KW; k++) {
            #pragma unroll
            for (int c = 0; c < CC; c++) {
                float xv = xs[tid + k][c];
                const float* wp = &ws[(k * CC + c) * FF + fo];
                #pragma unroll
                for (int j = 0; j < 8; j++) acc[j] = fmaf(xv, wp[j], acc[j]);
            }
        }
        #pragma unroll
        for (int j = 0; j < 8; j++) {
            int f = fo + j;
            float inv = rsqrtf(var[f] + 1e-3f);
            g_P[((size_t)b * FF + f) * TT + t] = (acc[j] - mean[f]) * inv * gamma[f] + beta[f];
        }
    }
}

// ---------------- Kernel 2: softmax over T ----------------
__global__ __launch_bounds__(256) void softmax_kernel()
{
    const int bf = blockIdx.x;
    float* row = g_P + (size_t)bf * TT;
    const int tid = threadIdx.x;

    float v[16];
    #pragma unroll
    for (int i = 0; i < 16; i++) v[i] = row[tid + i * 256];

    float m = v[0];
    #pragma unroll
    for (int i = 1; i < 16; i++) m = fmaxf(m, v[i]);

    __shared__ float sred[8];
    #pragma unroll
    for (int o = 16; o > 0; o >>= 1) m = fmaxf(m, __shfl_xor_sync(0xffffffffu, m, o));
    if ((tid & 31) == 0) sred[tid >> 5] = m;
    __syncthreads();
    m = sred[0];
    #pragma unroll
    for (int w = 1; w < 8; w++) m = fmaxf(m, sred[w]);

    float s = 0.f;
    #pragma unroll
    for (int i = 0; i < 16; i++) { v[i] = __expf(v[i] - m); s += v[i]; }
    #pragma unroll
    for (int o = 16; o > 0; o >>= 1) s += __shfl_xor_sync(0xffffffffu, s, o);
    __syncthreads();
    if ((tid & 31) == 0) sred[tid >> 5] = s;
    __syncthreads();
    s = 0.f;
    #pragma unroll
    for (int w = 0; w < 8; w++) s += sred[w];

    float inv = __fdividef(1.f, s);
    #pragma unroll
    for (int i = 0; i < 16; i++) row[tid + i * 256] = v[i] * inv;
}

// ---------------- Kernel 3: U = posenc @ W + bias (fp32 FFMA2; analytic posenc) ----------------
__global__ __launch_bounds__(256, 2) void u_gemm_kernel(
    const float* __restrict__ W,     // [F, L]
    const float* __restrict__ bias)  // [L]
{
    extern __shared__ __align__(16) float smem[];
    float (*Asm)[128] = (float(*)[128])smem;               // 64 k x 128 t
    float (*Wsm)[128] = (float(*)[128])(smem + 64 * 128);  // 64 k x 128 l
    __shared__ float ts[FF];

    const int tid  = threadIdx.x;
    const int tgrp = tid & 15;
    const int lgrp = tid >> 4;
    const int l0   = blockIdx.x * 128;
    const int tseg = blockIdx.y;

    if (tid < FF)
        ts[tid] = (float)pow(1.0e-4, (double)(tid & ~1) / 64.0);

    for (int i = tid; i < (64 * 128) / 4; i += 256) {
        int fr = i >> 5;
        int c4 = i & 31;
        *(float4*)&Wsm[fr][c4 * 4] = *(const float4*)&W[(size_t)fr * LL + l0 + c4 * 4];
    }

    ulonglong2 bq0 = *(const ulonglong2*)&bias[l0 + lgrp * 8];
    ulonglong2 bq1 = *(const ulonglong2*)&bias[l0 + lgrp * 8 + 4];
    unsigned long long bp[4] = {bq0.x, bq0.y, bq1.x, bq1.y};

    for (int ch = 0; ch < 4; ch++) {
        const int t0 = tseg * 512 + ch * 128;
        __syncthreads();
        for (int i = tid; i < 64 * 128; i += 256) {
            int k = i >> 7, t = i & 127;
            float ang = (float)(t0 + t) * ts[k];
            Asm[k][t] = (k & 1) ? cosf(ang) : sinf(ang);
        }
        __syncthreads();

        unsigned long long acc[8][4];
        #pragma unroll
        for (int i = 0; i < 8; i++)
            #pragma unroll
            for (int j = 0; j < 4; j++) acc[i][j] = bp[j];

        #pragma unroll 8
        for (int k = 0; k < 64; k++) {
            const ulonglong2* wq = (const ulonglong2*)&Wsm[k][lgrp * 8];
            ulonglong2 w01 = wq[0];
            ulonglong2 w23 = wq[1];
            float4 a0 = *(const float4*)&Asm[k][tgrp * 8];
            float4 a1 = *(const float4*)&Asm[k][tgrp * 8 + 4];
            float af[8] = {a0.x, a0.y, a0.z, a0.w, a1.x, a1.y, a1.z, a1.w};
            #pragma unroll
            for (int i = 0; i < 8; i++) {
                unsigned long long ap = packff(af[i], af[i]);
                ffma2(acc[i][0], ap, w01.x);
                ffma2(acc[i][1], ap, w01.y);
                ffma2(acc[i][2], ap, w23.x);
                ffma2(acc[i][3], ap, w23.y);
            }
        }

        #pragma unroll
        for (int i = 0; i < 8; i++) {
            float v0, v1, v2, v3, v4, v5, v6, v7;
            unpackff(acc[i][0], v0, v1);
            unpackff(acc[i][1], v2, v3);
            unpackff(acc[i][2], v4, v5);
            unpackff(acc[i][3], v6, v7);
            float* up = &g_U[(size_t)(t0 + tgrp * 8 + i) * LL + l0 + lgrp * 8];
            *(float4*)up       = make_float4(v0, v1, v2, v3);
            *(float4*)(up + 4) = make_float4(v4, v5, v6, v7);
        }
    }
}

// ---------------- Kernel 4: S = P @ W (tf32 mma, pipelined l-chunks); y = S + U; sigmoid; T-sum ----
// R12 structure; register diet (no U prefetch) + __launch_bounds__(256,3) for 24 warps/SM.
#define PS 68
#define SG_SMEM ((128 * PS + 2 * 64 * PS + 4 * 64) * 4)   // 70656 B

__global__ __launch_bounds__(256, 3) void sgemm_tc_kernel()
{
    extern __shared__ __align__(16) float sm[];
    float* Psm = sm;                          // [128 t][PS]
    float* red = sm + 128 * PS + 2 * 64 * PS; // [4][64]

    const int tid = threadIdx.x;
    const int b     = blockIdx.x;
    const int ttile = blockIdx.y;
    const int lq    = blockIdx.z;
    const int t0    = ttile * 128;
    const int lbase = lq * 1024;

    // fill Psm once: read coalesced along t, store [t][f] tf32
    for (int i = tid; i < 128 * 64; i += 256) {
        int f = i >> 7, t = i & 127;
        Psm[t * PS + f] = tf32r(g_P[((size_t)b * FF + f) * TT + t0 + t]);
    }

    const int lane = tid & 31;
    const int w    = tid >> 5;
    const int wt   = w & 3;           // t-warp (32 t)
    const int wl   = w >> 2;          // l-warp (32 l)
    const int g    = lane >> 2;
    const int tq   = lane & 3;

    const int rA = lane & 15;
    const int cA = (lane >> 4) * 16;
    const int rB = (lane & 7) + ((lane >> 4) & 1) * 8;
    const int cB = ((lane >> 3) & 1) * 16;

    const uint32_t sbP = smem_u32(Psm);
    const uint32_t sbW = sbP + 128 * PS * 4;
    uint32_t addrA0 = sbP + (uint32_t)((wt * 32 + rA) * PS) * 4 + cA;
    uint32_t addrA1 = addrA0 + 16 * PS * 4;

    // prologue: cp.async W chunk 0
    {
        const float* src = g_Wt + (size_t)lbase * FF;
        #pragma unroll
        for (int j = 0; j < 4; j++) {
            int i = tid + j * 256;
            int row = i >> 4, seg = i & 15;
            cp_async16(sbW + row * (PS * 4) + seg * 16, src + row * FF + seg * 4);
        }
        asm volatile("cp.async.commit_group;" ::: "memory");
    }

    const int tbase = t0 + wt * 32 + g;

    for (int c = 0; c < 16; c++) {
        asm volatile("cp.async.wait_group 0;" ::: "memory");
        __syncthreads();              // buf[c&1] ready; prior chunk's smem readers done

        const uint32_t wbuf = sbW + (uint32_t)(c & 1) * (64 * PS * 4);

        if (c + 1 < 16) {             // prefetch next W chunk into other buffer
            const float* src = g_Wt + (size_t)(lbase + (c + 1) * 64) * FF;
            uint32_t dst = sbW + (uint32_t)((c + 1) & 1) * (64 * PS * 4);
            #pragma unroll
            for (int j = 0; j < 4; j++) {
                int i = tid + j * 256;
                int row = i >> 4, seg = i & 15;
                cp_async16(dst + row * (PS * 4) + seg * 16, src + row * FF + seg * 4);
            }
            asm volatile("cp.async.commit_group;" ::: "memory");
        }

        const int l0    = lbase + c * 64;
        const int cbase = l0 + wl * 32 + 2 * tq;

        uint32_t addrB0 = wbuf + (uint32_t)((wl * 32 + rB) * PS) * 4 + cB;
        uint32_t addrB1 = addrB0 + 16 * PS * 4;

        float acc[2][4][4];
        #pragma unroll
        for (int m = 0; m < 2; m++)
            #pragma unroll
            for (int n = 0; n < 4; n++)
                #pragma unroll
                for (int j = 0; j < 4; j++) acc[m][n][j] = 0.f;

        #pragma unroll
        for (int ks = 0; ks < 8; ks++) {
            uint32_t fa0[4], fa1[4], fb0[4], fb1[4];
            ldsm_x4(fa0, addrA0 + ks * 32);
            ldsm_x4(fa1, addrA1 + ks * 32);
            ldsm_x4(fb0, addrB0 + ks * 32);
            ldsm_x4(fb1, addrB1 + ks * 32);
            mma_tf32(acc[0][0], fa0, &fb0[0]);
            mma_tf32(acc[0][1], fa0, &fb0[2]);
            mma_tf32(acc[0][2], fa0, &fb1[0]);
            mma_tf32(acc[0][3], fa0, &fb1[2]);
            mma_tf32(acc[1][0], fa1, &fb0[0]);
            mma_tf32(acc[1][1], fa1, &fb0[2]);
            mma_tf32(acc[1][2], fa1, &fb1[0]);
            mma_tf32(acc[1][3], fa1, &fb1[2]);
        }

        // epilogue: y = acc + U (direct L2 loads; latency hidden by 24 warps/SM);
        // d = (1-e^-y)/(1+e^-y); accumulate over t
        float colsum[8];
        #pragma unroll
        for (int i = 0; i < 8; i++) colsum[i] = 0.f;

        #pragma unroll
        for (int m = 0; m < 2; m++) {
            #pragma unroll
            for (int n = 0; n < 4; n++) {
                int col = cbase + n * 8;
                float2 u0 = *(const float2*)&g_U[(size_t)(tbase + m * 16) * LL + col];
                float2 u1 = *(const float2*)&g_U[(size_t)(tbase + m * 16 + 8) * LL + col];
                float y00 = acc[m][n][0] + u0.x;
                float y01 = acc[m][n][1] + u0.y;
                float y10 = acc[m][n][2] + u1.x;
                float y11 = acc[m][n][3] + u1.y;
                float e;
                e = __expf(-y00); colsum[2 * n]     += __fdividef(1.f - e, 1.f + e);
                e = __expf(-y10); colsum[2 * n]     += __fdividef(1.f - e, 1.f + e);
                e = __expf(-y01); colsum[2 * n + 1] += __fdividef(1.f - e, 1.f + e);
                e = __expf(-y11); colsum[2 * n + 1] += __fdividef(1.f - e, 1.f + e);
            }
        }

        #pragma unroll
        for (int off = 4; off <= 16; off <<= 1)
            #pragma unroll
            for (int i = 0; i < 8; i++)
                colsum[i] += __shfl_xor_sync(0xffffffffu, colsum[i], off);

        if (g == 0) {
            #pragma unroll
            for (int n = 0; n < 4; n++) {
                red[wt * 64 + wl * 32 + n * 8 + 2 * tq]     = colsum[2 * n];
                red[wt * 64 + wl * 32 + n * 8 + 2 * tq + 1] = colsum[2 * n + 1];
            }
        }
        __syncthreads();              // red writes visible
        if (tid < 64) {
            float s = red[tid] + red[64 + tid] + red[128 + tid] + red[192 + tid];
            g_part[((size_t)ttile * BB + b) * LL + l0 + tid] = s;
        }
        // top-of-loop sync separates these reads from next chunk's red writes
    }
}

// ---------------- Kernel 5: Gaussian shifting layer (banded) ----------------
__global__ __launch_bounds__(256) void warp_out_kernel(
    const float* __restrict__ x, float* __restrict__ out)
{
    const int idx = blockIdx.x * 256 + threadIdx.x;   // b*L + l
    const int b = idx >> 12;
    const int l = idx & (LL - 1);

    float sh = 0.f;
    #pragma unroll
    for (int s = 0; s < NTT; s++) sh += g_part[(size_t)s * BB * LL + idx];

    const float center = ((float)(l + 1) + sh) * ((float)TT / (float)LL);

    int tlo = (int)ceilf(center - 7.f);
    int thi = (int)floorf(center + 7.f);
    if (tlo < 1)  tlo = 1;
    if (thi > TT) thi = TT;

    float acc[8] = {0.f, 0.f, 0.f, 0.f, 0.f, 0.f, 0.f, 0.f};
    const float* xb = x + (size_t)b * TT * CC;
    for (int t = tlo; t <= thi; t++) {
        float d = (float)t - center;
        float wgt = __expf(-d * d);
        const float4* xp = (const float4*)(xb + (size_t)(t - 1) * CC);
        float4 x0 = xp[0];
        float4 x1 = xp[1];
        acc[0] = fmaf(wgt, x0.x, acc[0]);
        acc[1] = fmaf(wgt, x0.y, acc[1]);
        acc[2] = fmaf(wgt, x0.z, acc[2]);
        acc[3] = fmaf(wgt, x0.w, acc[3]);
        acc[4] = fmaf(wgt, x1.x, acc[4]);
        acc[5] = fmaf(wgt, x1.y, acc[5]);
        acc[6] = fmaf(wgt, x1.z, acc[6]);
        acc[7] = fmaf(wgt, x1.w, acc[7]);
    }

    const float inv = (float)(1.0 / 1.772637204826652);
    float4* op = (float4*)(out + (size_t)idx * CC);
    op[0] = make_float4(acc[0] * inv, acc[1] * inv, acc[2] * inv, acc[3] * inv);
    op[1] = make_float4(acc[4] * inv, acc[5] * inv, acc[6] * inv, acc[7] * inv);
}

// ---------------- launch ----------------
extern "C" void kernel_launch(void* const* d_in, const int* in_sizes, int n_in,
                              void* d_out, int out_size)
{
    const float* x       = (const float*)d_in[0];
    const float* conv_w  = (const float*)d_in[1];
    const float* conv_b  = (const float*)d_in[2];
    const float* gamma   = (const float*)d_in[3];
    const float* beta    = (const float*)d_in[4];
    const float* mean    = (const float*)d_in[5];
    const float* var     = (const float*)d_in[6];
    const float* dense_w = (const float*)d_in[7];
    const float* dense_b = (const float*)d_in[8];
    float* out = (float*)d_out;

    const int u_smem = 64 * 128 * sizeof(float) * 2;   // 64 KB
    cudaFuncSetAttribute(u_gemm_kernel,
                         cudaFuncAttributeMaxDynamicSharedMemorySize, u_smem);
    cudaFuncSetAttribute(sgemm_tc_kernel,
                         cudaFuncAttributeMaxDynamicSharedMemorySize, SG_SMEM);

    prep_wt_kernel<<<(FF * LL) / 256, 256>>>(dense_w);
    conv_bn_kernel<<<dim3(TT / 256, BB), 256>>>(x, conv_w, conv_b, gamma, beta, mean, var);
    softmax_kernel<<<BB * FF, 256>>>();
    u_gemm_kernel<<<dim3(LL / 128, TT / 512), 256, u_smem>>>(dense_w, dense_b);
    sgemm_tc_kernel<<<dim3(BB, NTT, 4), 256, SG_SMEM>>>();
    warp_out_kernel<<<(BB * LL) / 256, 256>>>(x, out);
}